// round 17
// baseline (speedup 1.0000x reference)
#include <cuda_runtime.h>
#include <cuda_bf16.h>
#include <math.h>
#include <stdint.h>

#define BB 4096
#define EE 128
#define MMOD 8
#define NSTEPS 3
#define HDIM 256
#define CDIM 16
#define TILE 64
#define NTHR 256
#define NTHR2 512
#define MAXT 72

#define S128B 272     // row stride (bytes) for gathered A tiles (K=128)
#define SCH   144     // row stride inside one K-chunk (64 cols *2B + 16 pad)
#define WCH1  18432   // K-chunk of a 128-row image (128*144)
#define HCH   9216    // K-chunk of a 64-row image  (64*144)
#define W2CH  2304    // K-chunk of the 16-row W2 image (16*144)
#define HIMG  36864   // per-tile H image = 4 chunks * HCH

// P1 smem: A hi/lo (S128B) + W hi/lo (2 K-chunks each)
#define P1_AH 0
#define P1_AL 17408
#define P1_WH 34816
#define P1_WL 71680
#define P1_SMEM 108544
// P2 smem: H hi/lo (4 chunks) + Wf-half hi/lo (4 chunks)
#define P2_HH 0
#define P2_HL 36864
#define P2_WH 73728
#define P2_WL 110592
#define P2_SMEM 147456
// head P2 smem
#define HP2_HH 0
#define HP2_HL 36864
#define HP2_WH 73728
#define HP2_WL 82944
#define HP2_SMEM 92160

// ---------------- global scratch ------------------------------------------
__device__ uint32_t g_Xpair[2][BB * 64];            // state: packed bf16 hi/lo
__device__ int g_order[NSTEPS * BB];
__device__ int g_tiles[NSTEPS * MAXT * 3];
__device__ __align__(256) uint8_t g_Himg[2][MAXT * HIMG];
__device__ __align__(256) uint8_t g_WinT[2][MMOD * 36864];  // 2 K-chunks x 128 rows
__device__ __align__(256) uint8_t g_WbiT[2][MMOD * 36864];
__device__ __align__(256) uint8_t g_WfT [2][MMOD * 73728];  // 2 halves x 4 chunks x 64 rows
__device__ __align__(256) uint8_t g_W1T [2][73728];         // 2 halves x 2 chunks x 128 rows
__device__ __align__(256) uint8_t g_W2T [2][9216];          // 4 chunks x 16 rows

// ---------------- helpers ---------------------------------------------------
__device__ __forceinline__ uint32_t sptr(const void* p) {
    return (uint32_t)__cvta_generic_to_shared(p);
}
__device__ __forceinline__ void sts32(uint32_t a, uint32_t v) {
    asm volatile("st.shared.b32 [%0], %1;" :: "r"(a), "r"(v) : "memory");
}
__device__ __forceinline__ void mbar_init(uint32_t mb, uint32_t cnt) {
    asm volatile("mbarrier.init.shared.b64 [%0], %1;" :: "r"(mb), "r"(cnt) : "memory");
}
__device__ __forceinline__ void mbar_expect(uint32_t mb, uint32_t bytes) {
    asm volatile("mbarrier.arrive.expect_tx.shared.b64 _, [%0], %1;" :: "r"(mb), "r"(bytes) : "memory");
}
__device__ __forceinline__ void tma_bulk(uint32_t dst, const void* src, uint32_t bytes, uint32_t mb) {
    asm volatile("cp.async.bulk.shared::cluster.global.mbarrier::complete_tx::bytes [%0], [%1], %2, [%3];"
                 :: "r"(dst), "l"(src), "r"(bytes), "r"(mb) : "memory");
}
__device__ __forceinline__ void mbar_wait(uint32_t mb, uint32_t parity) {
    asm volatile(
        "{\n\t.reg .pred P1;\n\t"
        "WL_%=:\n\t"
        "mbarrier.try_wait.parity.acquire.cta.shared::cta.b64 P1, [%0], %1, 0x989680;\n\t"
        "@P1 bra.uni WD_%=;\n\t"
        "bra.uni WL_%=;\n\t"
        "WD_%=:\n\t}" :: "r"(mb), "r"(parity) : "memory");
}
__device__ __forceinline__ void splitf(float v0, float v1, uint32_t& h, uint32_t& l) {
    __nv_bfloat16 h0 = __float2bfloat16(v0), h1 = __float2bfloat16(v1);
    float r0 = v0 - __bfloat162float(h0), r1 = v1 - __bfloat162float(h1);
    __nv_bfloat16 l0 = __float2bfloat16(r0), l1 = __float2bfloat16(r1);
    h = (uint32_t)__bfloat16_as_ushort(h0) | ((uint32_t)__bfloat16_as_ushort(h1) << 16);
    l = (uint32_t)__bfloat16_as_ushort(l0) | ((uint32_t)__bfloat16_as_ushort(l1) << 16);
}
__device__ __forceinline__ void ldsm4(uint32_t* a, uint32_t addr) {
    asm volatile("ldmatrix.sync.aligned.m8n8.x4.shared.b16 {%0,%1,%2,%3}, [%4];"
                 : "=r"(a[0]), "=r"(a[1]), "=r"(a[2]), "=r"(a[3]) : "r"(addr));
}
__device__ __forceinline__ void ldsm2(uint32_t& b0, uint32_t& b1, uint32_t addr) {
    asm volatile("ldmatrix.sync.aligned.m8n8.x2.shared.b16 {%0,%1}, [%2];"
                 : "=r"(b0), "=r"(b1) : "r"(addr));
}
__device__ __forceinline__ void mma4(float* c, const uint32_t* a, uint32_t b0, uint32_t b1) {
    asm volatile("mma.sync.aligned.m16n8k16.row.col.f32.bf16.bf16.f32 "
                 "{%0,%1,%2,%3},{%4,%5,%6,%7},{%8,%9},{%0,%1,%2,%3};"
                 : "+f"(c[0]), "+f"(c[1]), "+f"(c[2]), "+f"(c[3])
                 : "r"(a[0]), "r"(a[1]), "r"(a[2]), "r"(a[3]), "r"(b0), "r"(b1));
}

// Single-M-stripe fragment-reuse warp GEMM over one K-chunk (KC k-steps).
// A at stride SBA with byte offset akb0; B chunk-local at stride SBB.
template<int NT, int KC, int SBA, int SBB>
__device__ __forceinline__ void wgemm1(float* acc,
                                       uint32_t aHI, uint32_t aLO,
                                       uint32_t bHI, uint32_t bLO,
                                       int mbase, int nbase, int lane, int akb0) {
    const uint32_t aoff = (uint32_t)(mbase + (lane & 15)) * SBA + ((lane >> 4) * 16) + akb0;
    const uint32_t boff = (uint32_t)(nbase + (lane & 7)) * SBB + (((lane >> 3) & 1) * 16);
    const uint32_t AH = aHI + aoff, AL = aLO + aoff;
    const uint32_t BH = bHI + boff, BL = bLO + boff;
#pragma unroll
    for (int k = 0; k < KC; k++) {
        uint32_t ah[4], al[4];
        ldsm4(ah, AH + k * 32);
        ldsm4(al, AL + k * 32);
#pragma unroll
        for (int nt = 0; nt < NT; nt++) {
            uint32_t bh0, bh1, bl0, bl1;
            ldsm2(bh0, bh1, BH + nt * 8 * SBB + k * 32);
            ldsm2(bl0, bl1, BL + nt * 8 * SBB + k * 32);
            float* c = acc + nt * 4;
            mma4(c, ah, bh0, bh1);
            mma4(c, ah, bl0, bl1);
            mma4(c, al, bh0, bh1);
        }
    }
}
// Two-M-stripe variant (head_p2), chunk-local both operands.
template<int NT, int KC, int SBA, int SBB>
__device__ __forceinline__ void wgemm2(float* acc,
                                       uint32_t aHI, uint32_t aLO,
                                       uint32_t bHI, uint32_t bLO,
                                       int mbase, int nbase, int lane) {
    const uint32_t aoff = (uint32_t)(mbase + (lane & 15)) * SBA + ((lane >> 4) * 16);
    const uint32_t boff = (uint32_t)(nbase + (lane & 7)) * SBB + (((lane >> 3) & 1) * 16);
    const uint32_t AH = aHI + aoff, AL = aLO + aoff;
    const uint32_t BH = bHI + boff, BL = bLO + boff;
#pragma unroll
    for (int k = 0; k < KC; k++) {
        uint32_t ah0[4], ah1[4], al0[4], al1[4];
        ldsm4(ah0, AH + k * 32);
        ldsm4(ah1, AH + 16 * SBA + k * 32);
        ldsm4(al0, AL + k * 32);
        ldsm4(al1, AL + 16 * SBA + k * 32);
#pragma unroll
        for (int nt = 0; nt < NT; nt++) {
            uint32_t bh0, bh1, bl0, bl1;
            ldsm2(bh0, bh1, BH + nt * 8 * SBB + k * 32);
            ldsm2(bl0, bl1, BL + nt * 8 * SBB + k * 32);
            float* c0 = acc + (0 * NT + nt) * 4;
            float* c1 = acc + (1 * NT + nt) * 4;
            mma4(c0, ah0, bh0, bh1);
            mma4(c1, ah1, bh0, bh1);
            mma4(c0, ah0, bl0, bl1);
            mma4(c1, ah1, bl0, bl1);
            mma4(c0, al0, bh0, bh1);
            mma4(c1, al1, bh0, bh1);
        }
    }
}

// ---------------------------------------------------------------------------
__global__ void setup_kernel(const int* __restrict__ module_ids) {
    __shared__ int cnt[MMOD], cur[MMOD];
    int tid = threadIdx.x, s = blockIdx.x, lane = tid & 31;
    if (tid < MMOD) cnt[tid] = 0;
    __syncthreads();
    for (int b = tid; b < BB; b += NTHR) {
        int m = module_ids[b * NSTEPS + s];
        unsigned mask = __match_any_sync(0xffffffffu, m);
        int leader = __ffs(mask) - 1;
        if (lane == leader) atomicAdd(&cnt[m], __popc(mask));
    }
    __syncthreads();
    if (tid == 0) {
        int o = 0, t = 0;
        for (int m = 0; m < MMOD; m++) {
            cur[m] = o;
            int c = cnt[m];
            for (int ch = 0; ch < c; ch += TILE) {
                g_tiles[(s * MAXT + t) * 3 + 0] = m;
                g_tiles[(s * MAXT + t) * 3 + 1] = o + ch;
                g_tiles[(s * MAXT + t) * 3 + 2] = min(TILE, c - ch);
                t++;
            }
            o += c;
        }
        for (; t < MAXT; t++) g_tiles[(s * MAXT + t) * 3 + 2] = 0;
    }
    __syncthreads();
    for (int b = tid; b < BB; b += NTHR) {
        int m = module_ids[b * NSTEPS + s];
        unsigned mask = __match_any_sync(0xffffffffu, m);
        int leader = __ffs(mask) - 1;
        int base = 0;
        if (lane == leader) base = atomicAdd(&cur[m], __popc(mask));
        base = __shfl_sync(mask, base, leader);
        int pos = base + __popc(mask & ((1u << lane) - 1u));
        g_order[s * BB + pos] = b;
    }
}

// Build transposed, hi/lo-split, K-chunked weight images.
__global__ void xform_kernel(const float* __restrict__ W_in,
                             const float* __restrict__ W_bias,
                             const float* __restrict__ W_f,
                             const float* __restrict__ W1,
                             const float* __restrict__ W2) {
    int j = blockIdx.y;
    const float* src; uint8_t *dh, *dl; int R, C;
    if (j < 8)       { src = W_in + j * 16384;  dh = g_WinT[0] + j * 36864; dl = g_WinT[1] + j * 36864; R = 128; C = 128; }
    else if (j < 16) { int q = j - 8;  src = W_bias + q * 16384; dh = g_WbiT[0] + q * 36864; dl = g_WbiT[1] + q * 36864; R = 128; C = 128; }
    else if (j < 24) { int q = j - 16; src = W_f + q * 32768;    dh = g_WfT[0] + q * 73728;  dl = g_WfT[1] + q * 73728;  R = 128; C = 256; }
    else if (j == 24){ src = W1; dh = g_W1T[0]; dl = g_W1T[1]; R = 256; C = 128; }
    else             { src = W2; dh = g_W2T[0]; dl = g_W2T[1]; R = 16;  C = 256; }
    int units = R * C / 2;
    for (int u = blockIdx.x * NTHR + threadIdx.x; u < units; u += gridDim.x * NTHR) {
        int rr = u % R, cc = (u / R) * 2;
        float v0 = src[(size_t)cc * R + rr];
        float v1 = src[(size_t)(cc + 1) * R + rr];
        uint32_t h, l;
        splitf(v0, v1, h, l);
        size_t off;
        if (j < 16)       off = (size_t)(cc >> 6) * WCH1 + (size_t)rr * SCH + (cc & 63) * 2;
        else if (j < 24)  off = (size_t)(rr >> 6) * 36864 + (size_t)(cc >> 6) * HCH + (rr & 63) * SCH + (cc & 63) * 2;
        else if (j == 24) off = (size_t)(rr >> 7) * 36864 + (size_t)(cc >> 6) * WCH1 + (rr & 127) * SCH + (cc & 63) * 2;
        else              off = (size_t)(cc >> 6) * W2CH + (size_t)rr * SCH + (cc & 63) * 2;
        *(uint32_t*)(dh + off) = h;
        *(uint32_t*)(dl + off) = l;
    }
}

// ---------------------------------------------------------------------------
// Step P1: CTA = (tile, half). W in 2 K-chunks, progressive. grid 144.
// ---------------------------------------------------------------------------
__global__ __launch_bounds__(NTHR2)
void step_p1(int s, const float* __restrict__ emb, const int* __restrict__ eids,
             const float* __restrict__ b_in, const float* __restrict__ b_bias) {
    extern __shared__ uint8_t raw[];
    const uint32_t base = sptr(raw);
    __shared__ int srow[TILE];
    __shared__ float sb[EE];
    __shared__ __align__(8) uint64_t mbar[2];
    int tid = threadIdx.x, wid = tid >> 5, lane = tid & 31;
    int t = blockIdx.x >> 1, h = blockIdx.x & 1;

    int m   = g_tiles[(s * MAXT + t) * 3 + 0];
    int bse = g_tiles[(s * MAXT + t) * 3 + 1];
    int cnt = g_tiles[(s * MAXT + t) * 3 + 2];
    if (cnt == 0) return;

    const uint8_t* WH = (h ? g_WbiT[0] : g_WinT[0]) + m * 36864;
    const uint8_t* WL = (h ? g_WbiT[1] : g_WinT[1]) + m * 36864;
    if (tid == 0) {
#pragma unroll
        for (int c = 0; c < 2; c++) {
            uint32_t mb = sptr(&mbar[c]);
            mbar_init(mb, 1);
            mbar_expect(mb, 2 * WCH1);
            tma_bulk(base + P1_WH + c * WCH1, WH + c * WCH1, WCH1, mb);
            tma_bulk(base + P1_WL + c * WCH1, WL + c * WCH1, WCH1, mb);
        }
    }
    if (tid < TILE) {
        int row = g_order[s * BB + bse + (tid < cnt ? tid : 0)];
        srow[tid] = h ? eids[row * (NSTEPS + 1) + s + 1]
                      : ((s == 0) ? eids[row * (NSTEPS + 1)] : row);
    }
    if (tid < EE) sb[tid] = h ? b_bias[m * EE + tid] : b_in[m * EE + tid];
    __syncthreads();

    const bool frompair = (h == 0 && s > 0);
    for (int i = tid; i < TILE * 64; i += NTHR2) {
        int r = i >> 6, k = i & 63;
        uint32_t hh, ll;
        if (frompair) {
            hh = g_Xpair[0][srow[r] * 64 + k];
            ll = g_Xpair[1][srow[r] * 64 + k];
        } else {
            float2 v = *(const float2*)&emb[(size_t)srow[r] * EE + 2 * k];
            splitf(v.x, v.y, hh, ll);
        }
        sts32(base + P1_AH + r * S128B + k * 4, hh);
        sts32(base + P1_AL + r * S128B + k * 4, ll);
    }
    __syncthreads();   // A-tile visible

    const int mh = wid >> 2, nq = wid & 3;
    const int g = lane >> 2, cp = (lane & 3) * 2;
    float acc[4 * 4];
#pragma unroll
    for (int i = 0; i < 16; i++) acc[i] = 0.f;
#pragma unroll
    for (int c = 0; c < 2; c++) {
        mbar_wait(sptr(&mbar[c]), 0);
        wgemm1<4, 4, S128B, SCH>(acc, base + P1_AH, base + P1_AL,
                                 base + P1_WH + c * WCH1, base + P1_WL + c * WCH1,
                                 mh * 16, nq * 32, lane, c * 128);
    }

    uint8_t* HB0 = g_Himg[0] + t * HIMG;
    uint8_t* HB1 = g_Himg[1] + t * HIMG;
#pragma unroll
    for (int nt = 0; nt < 4; nt++) {
        int r0 = mh * 16 + g;
        int cw = nq * 32 + nt * 8 + cp;        // local col within this half
        int cg = h * 128 + cw;                 // global f col
        size_t off0 = (size_t)(cg >> 6) * HCH + (size_t)r0 * SCH + (cg & 63) * 2;
        size_t off1 = (size_t)(cg >> 6) * HCH + (size_t)(r0 + 8) * SCH + (cg & 63) * 2;
        float* c = acc + nt * 4;
        uint32_t hh, ll;
        splitf(fmaxf(c[0] + sb[cw], 0.f), fmaxf(c[1] + sb[cw + 1], 0.f), hh, ll);
        *(uint32_t*)(HB0 + off0) = hh;
        *(uint32_t*)(HB1 + off0) = ll;
        splitf(fmaxf(c[2] + sb[cw], 0.f), fmaxf(c[3] + sb[cw + 1], 0.f), hh, ll);
        *(uint32_t*)(HB0 + off1) = hh;
        *(uint32_t*)(HB1 + off1) = ll;
    }
}

// ---------------------------------------------------------------------------
// Step P2: CTA = (tile, N-half). H + W in 4 K-chunks, progressive. grid 144.
// ---------------------------------------------------------------------------
__global__ __launch_bounds__(NTHR2)
void step_p2(int s, const float* __restrict__ b_f) {
    extern __shared__ uint8_t raw[];
    const uint32_t base = sptr(raw);
    __shared__ int ridx[TILE];
    __shared__ float sb[TILE];
    __shared__ __align__(8) uint64_t mbar[4];
    int tid = threadIdx.x, wid = tid >> 5, lane = tid & 31;
    int t = blockIdx.x >> 1, nh = blockIdx.x & 1;

    int m   = g_tiles[(s * MAXT + t) * 3 + 0];
    int bse = g_tiles[(s * MAXT + t) * 3 + 1];
    int cnt = g_tiles[(s * MAXT + t) * 3 + 2];
    if (cnt == 0) return;

    const uint8_t* H0 = g_Himg[0] + t * HIMG;
    const uint8_t* H1 = g_Himg[1] + t * HIMG;
    const uint8_t* W0 = g_WfT[0] + m * 73728 + nh * 36864;
    const uint8_t* W1p = g_WfT[1] + m * 73728 + nh * 36864;
    if (tid == 0) {
#pragma unroll
        for (int c = 0; c < 4; c++) {
            uint32_t mb = sptr(&mbar[c]);
            mbar_init(mb, 1);
            mbar_expect(mb, 4 * HCH);
            tma_bulk(base + P2_HH + c * HCH, H0 + c * HCH, HCH, mb);
            tma_bulk(base + P2_HL + c * HCH, H1 + c * HCH, HCH, mb);
            tma_bulk(base + P2_WH + c * HCH, W0 + c * HCH, HCH, mb);
            tma_bulk(base + P2_WL + c * HCH, W1p + c * HCH, HCH, mb);
        }
    }
    if (tid < TILE) {
        ridx[tid] = g_order[s * BB + bse + (tid < cnt ? tid : 0)];
        sb[tid] = b_f[m * EE + nh * 64 + tid];
    }
    __syncthreads();

    const int mh = wid >> 2, nq = wid & 3;
    const int g = lane >> 2, cp = (lane & 3) * 2;
    float acc[2 * 4];
#pragma unroll
    for (int i = 0; i < 8; i++) acc[i] = 0.f;
#pragma unroll
    for (int c = 0; c < 4; c++) {
        mbar_wait(sptr(&mbar[c]), 0);
        wgemm1<2, 4, SCH, SCH>(acc, base + P2_HH + c * HCH, base + P2_HL + c * HCH,
                               base + P2_WH + c * HCH, base + P2_WL + c * HCH,
                               mh * 16, nq * 16, lane, 0);
    }

#pragma unroll
    for (int nt = 0; nt < 2; nt++) {
        int r0 = mh * 16 + g;
        int cl = nq * 16 + nt * 8 + cp;
        int cg = nh * 64 + cl;
        float* c = acc + nt * 4;
        uint32_t hh, ll;
        if (r0 < cnt) {
            int gr = ridx[r0];
            splitf(tanhf(c[0] + sb[cl]), tanhf(c[1] + sb[cl + 1]), hh, ll);
            g_Xpair[0][gr * 64 + (cg >> 1)] = hh;
            g_Xpair[1][gr * 64 + (cg >> 1)] = ll;
        }
        if (r0 + 8 < cnt) {
            int gr = ridx[r0 + 8];
            splitf(tanhf(c[2] + sb[cl]), tanhf(c[3] + sb[cl + 1]), hh, ll);
            g_Xpair[0][gr * 64 + (cg >> 1)] = hh;
            g_Xpair[1][gr * 64 + (cg >> 1)] = ll;
        }
    }
}

// ---------------------------------------------------------------------------
// Head P1: CTA = (tile, j-half). W1T half in 2 K-chunks, progressive. grid 128.
// ---------------------------------------------------------------------------
__global__ __launch_bounds__(NTHR2)
void head_p1(const float* __restrict__ b1) {
    extern __shared__ uint8_t raw[];
    const uint32_t base = sptr(raw);
    __shared__ float sb[EE];
    __shared__ __align__(8) uint64_t mbar[2];
    int tid = threadIdx.x, wid = tid >> 5, lane = tid & 31;
    int t = blockIdx.x >> 1, h = blockIdx.x & 1;
    int row0 = t * TILE;

    const uint8_t* WH = g_W1T[0] + h * 36864;
    const uint8_t* WL = g_W1T[1] + h * 36864;
    if (tid == 0) {
#pragma unroll
        for (int c = 0; c < 2; c++) {
            uint32_t mb = sptr(&mbar[c]);
            mbar_init(mb, 1);
            mbar_expect(mb, 2 * WCH1);
            tma_bulk(base + P1_WH + c * WCH1, WH + c * WCH1, WCH1, mb);
            tma_bulk(base + P1_WL + c * WCH1, WL + c * WCH1, WCH1, mb);
        }
    }
    if (tid < EE) sb[tid] = b1[h * EE + tid];
    __syncthreads();

    for (int i = tid; i < TILE * 64; i += NTHR2) {
        int r = i >> 6, k = i & 63;
        sts32(base + P1_AH + r * S128B + k * 4, g_Xpair[0][(row0 + r) * 64 + k]);
        sts32(base + P1_AL + r * S128B + k * 4, g_Xpair[1][(row0 + r) * 64 + k]);
    }
    __syncthreads();

    const int mh = wid >> 2, nq = wid & 3;
    const int g = lane >> 2, cp = (lane & 3) * 2;
    float acc[4 * 4];
#pragma unroll
    for (int i = 0; i < 16; i++) acc[i] = 0.f;
#pragma unroll
    for (int c = 0; c < 2; c++) {
        mbar_wait(sptr(&mbar[c]), 0);
        wgemm1<4, 4, S128B, SCH>(acc, base + P1_AH, base + P1_AL,
                                 base + P1_WH + c * WCH1, base + P1_WL + c * WCH1,
                                 mh * 16, nq * 32, lane, c * 128);
    }

    uint8_t* HB0 = g_Himg[0] + t * HIMG;
    uint8_t* HB1 = g_Himg[1] + t * HIMG;
#pragma unroll
    for (int nt = 0; nt < 4; nt++) {
        int r0 = mh * 16 + g;
        int cw = nq * 32 + nt * 8 + cp;
        int cg = h * 128 + cw;
        size_t off0 = (size_t)(cg >> 6) * HCH + (size_t)r0 * SCH + (cg & 63) * 2;
        size_t off1 = (size_t)(cg >> 6) * HCH + (size_t)(r0 + 8) * SCH + (cg & 63) * 2;
        float* c = acc + nt * 4;
        uint32_t hh, ll;
        splitf(fmaxf(c[0] + sb[cw], 0.f), fmaxf(c[1] + sb[cw + 1], 0.f), hh, ll);
        *(uint32_t*)(HB0 + off0) = hh;
        *(uint32_t*)(HB1 + off0) = ll;
        splitf(fmaxf(c[2] + sb[cw], 0.f), fmaxf(c[3] + sb[cw + 1], 0.f), hh, ll);
        *(uint32_t*)(HB0 + off1) = hh;
        *(uint32_t*)(HB1 + off1) = ll;
    }
}

// ---------------------------------------------------------------------------
// Head P2: out tile = H @ W2 + b2. 4 K-chunks, progressive. grid 64, 256 thr.
// ---------------------------------------------------------------------------
__global__ __launch_bounds__(NTHR)
void head_p2(const float* __restrict__ b2, float* __restrict__ out) {
    extern __shared__ uint8_t raw[];
    const uint32_t base = sptr(raw);
    __shared__ float sb2[CDIM];
    __shared__ __align__(8) uint64_t mbar[4];
    int tid = threadIdx.x, wid = tid >> 5, lane = tid & 31;
    int t = blockIdx.x;
    int row0 = t * TILE;

    if (tid == 0) {
#pragma unroll
        for (int c = 0; c < 4; c++) {
            uint32_t mb = sptr(&mbar[c]);
            mbar_init(mb, 1);
            mbar_expect(mb, 2 * HCH + 2 * W2CH);
            tma_bulk(base + HP2_HH + c * HCH, g_Himg[0] + t * HIMG + c * HCH, HCH, mb);
            tma_bulk(base + HP2_HL + c * HCH, g_Himg[1] + t * HIMG + c * HCH, HCH, mb);
            tma_bulk(base + HP2_WH + c * W2CH, g_W2T[0] + c * W2CH, W2CH, mb);
            tma_bulk(base + HP2_WL + c * W2CH, g_W2T[1] + c * W2CH, W2CH, mb);
        }
    }
    if (tid < CDIM) sb2[tid] = b2[tid];
    __syncthreads();

    if (wid < 4) {
        const int mh = wid >> 1, nq = wid & 1;
        const int g = lane >> 2, cp = (lane & 3) * 2;
        float acc[2 * 1 * 4];
#pragma unroll
        for (int i = 0; i < 8; i++) acc[i] = 0.f;
#pragma unroll
        for (int c = 0; c < 4; c++) {
            mbar_wait(sptr(&mbar[c]), 0);
            wgemm2<1, 4, SCH, SCH>(acc, base + HP2_HH + c * HCH, base + HP2_HL + c * HCH,
                                   base + HP2_WH + c * W2CH, base + HP2_WL + c * W2CH,
                                   mh * 32, nq * 8, lane);
        }
#pragma unroll
        for (int ms = 0; ms < 2; ms++) {
            int r = row0 + mh * 32 + ms * 16 + g;
            int c0 = nq * 8 + cp;
            float* c = acc + ms * 4;
            out[r * CDIM + c0]           = c[0] + sb2[c0];
            out[r * CDIM + c0 + 1]       = c[1] + sb2[c0 + 1];
            out[(r + 8) * CDIM + c0]     = c[2] + sb2[c0];
            out[(r + 8) * CDIM + c0 + 1] = c[3] + sb2[c0 + 1];
        }
    }
}

// ---------------------------------------------------------------------------
extern "C" void kernel_launch(void* const* d_in, const int* in_sizes, int n_in,
                              void* d_out, int out_size) {
    const int*   entity_ids = (const int*)d_in[0];
    const int*   module_ids = (const int*)d_in[1];
    const float* emb        = (const float*)d_in[2];
    const float* W_in       = (const float*)d_in[3];
    const float* b_in       = (const float*)d_in[4];
    const float* W_bias     = (const float*)d_in[5];
    const float* b_bias     = (const float*)d_in[6];
    const float* W_f        = (const float*)d_in[7];
    const float* b_f        = (const float*)d_in[8];
    const float* W1         = (const float*)d_in[9];
    const float* b1         = (const float*)d_in[10];
    const float* W2         = (const float*)d_in[11];
    const float* b2         = (const float*)d_in[12];
    float* out = (float*)d_out;

    cudaFuncSetAttribute(step_p1, cudaFuncAttributeMaxDynamicSharedMemorySize, P1_SMEM);
    cudaFuncSetAttribute(step_p2, cudaFuncAttributeMaxDynamicSharedMemorySize, P2_SMEM);
    cudaFuncSetAttribute(head_p1, cudaFuncAttributeMaxDynamicSharedMemorySize, P1_SMEM);
    cudaFuncSetAttribute(head_p2, cudaFuncAttributeMaxDynamicSharedMemorySize, HP2_SMEM);

    setup_kernel<<<NSTEPS, NTHR>>>(module_ids);
    xform_kernel<<<dim3(32, 26), NTHR>>>(W_in, W_bias, W_f, W1, W2);
    for (int s = 0; s < NSTEPS; s++) {
        step_p1<<<2 * MAXT, NTHR2, P1_SMEM>>>(s, emb, entity_ids, b_in, b_bias);
        step_p2<<<2 * MAXT, NTHR2, P2_SMEM>>>(s, b_f);
    }
    head_p1<<<2 * (BB / TILE), NTHR2, P1_SMEM>>>(b1);
    head_p2<<<BB / TILE, NTHR, HP2_SMEM>>>(b2, out);
}